// round 13
// baseline (speedup 1.0000x reference)
#include <cuda_runtime.h>
#include <cuda_fp16.h>
#include <math.h>

#define Bsz 128
#define Nn  512
#define Dd  64
#define KTOP 20
#define FULLMASK 0xFFFFFFFFu
#define NEG_SLOPE 0.2f
#define BN_EPS 1e-5f

typedef unsigned long long ull;

// ---------------- scratch (device globals; no allocations) ----------------
__device__ __align__(16) __half2 g_z_h[Bsz*Nn*32];    // z as half2 (8.4MB)
__device__ __align__(16) __half2 g_rst_h[Bsz*Nn*32];  // rst as half2 (8.4MB)
__device__ __align__(16) float g_cos[Nn*Nn];          // 1 MB
__device__ float g_zsrc[Bsz*Nn];
__device__ float g_zdst[Bsz*Nn];
__device__ int   g_srcJ[KTOP*Nn];                     // j-major: srcJ[j][d]
__device__ float g_esrc[Nn];
__device__ float g_edst[Nn];
__device__ __align__(16) float g_sum[Dd];
__device__ __align__(16) float g_sumsq[Dd];

// ---------------- f32x2 packed helpers -------------------------------------
__device__ __forceinline__ ull pack2(float x, float y) {
    ull r; asm("mov.b64 %0, {%1, %2};" : "=l"(r) : "f"(x), "f"(y)); return r;
}
__device__ __forceinline__ void fma2(ull& d, ull a, ull b) {
    asm("fma.rn.f32x2 %0, %1, %2, %0;" : "+l"(d) : "l"(a), "l"(b));
}
__device__ __forceinline__ float2 unpack2(ull v) {
    float2 r; asm("mov.b64 {%0, %1}, %2;" : "=f"(r.x), "=f"(r.y) : "l"(v)); return r;
}

// ===========================================================================
// KGEMM: z-GEMM (R12 GEMM branch as uniform kernel). 1024 CTAs x 256 thr.
// Register epilogue: z -> gmem fp16 + zsrc/zdst via shfl tree.
// ===========================================================================
__global__ void __launch_bounds__(256)
kgemm(const float* __restrict__ data,
      const float* __restrict__ fc_w,
      const float* __restrict__ fc_b,
      const float* __restrict__ attn_w) {
    extern __shared__ float sm[];
    float* At  = sm;                      // 64*68 fp32
    ull*   wP  = (ull*)(sm + 4352);       // 64*34 packed w pairs
    float* aws = sm + 8704;               // 64
    float* awd = aws + 64;                // 64
    float* bias= awd + 64;                // 64  (ends at 8896)
    int tid = threadIdx.x;
    int m0 = blockIdx.x * 64;

    if (blockIdx.x == 0 && tid >= 128 && tid < 256) {
        int t = tid - 128;
        if (t < 64) g_sum[t] = 0.f; else g_sumsq[t - 64] = 0.f;
    }
    for (int idx = tid; idx < 1024; idx += 256) {
        int r = idx >> 4, kq = idx & 15;
        float4 v = *(const float4*)&data[(m0 + r)*64 + 4*kq];
        At[(4*kq+0)*68 + r] = v.x;
        At[(4*kq+1)*68 + r] = v.y;
        At[(4*kq+2)*68 + r] = v.z;
        At[(4*kq+3)*68 + r] = v.w;
    }
    for (int idx = tid; idx < 512; idx += 256) {
        int cp = idx >> 4, kq = idx & 15;
        float4 lo = *(const float4*)&fc_w[(2*cp)*64 + 4*kq];
        float4 hi = *(const float4*)&fc_w[(2*cp+1)*64 + 4*kq];
        wP[(4*kq+0)*34 + cp] = pack2(lo.x, hi.x);
        wP[(4*kq+1)*34 + cp] = pack2(lo.y, hi.y);
        wP[(4*kq+2)*34 + cp] = pack2(lo.z, hi.z);
        wP[(4*kq+3)*34 + cp] = pack2(lo.w, hi.w);
    }
    if (tid < 64) {
        bias[tid] = fc_b[tid];
        aws[tid]  = attn_w[tid];
        awd[tid]  = attn_w[128 + tid];
    }
    __syncthreads();

    int tx = tid & 15, ty = tid >> 4;
    int r0 = ty * 4;
    ull acc[4][2] = {};
#pragma unroll 8
    for (int k = 0; k < 64; ++k) {
        float4 a4 = *(const float4*)&At[k*68 + r0];
        ulonglong2 w2 = *(const ulonglong2*)&wP[k*34 + 2*tx];
        ull pa0 = pack2(a4.x, a4.x), pa1 = pack2(a4.y, a4.y);
        ull pa2 = pack2(a4.z, a4.z), pa3 = pack2(a4.w, a4.w);
        fma2(acc[0][0], pa0, w2.x); fma2(acc[0][1], pa0, w2.y);
        fma2(acc[1][0], pa1, w2.x); fma2(acc[1][1], pa1, w2.y);
        fma2(acc[2][0], pa2, w2.x); fma2(acc[2][1], pa2, w2.y);
        fma2(acc[3][0], pa3, w2.x); fma2(acc[3][1], pa3, w2.y);
    }
    // register epilogue
    int c0 = 4 * tx;
    float4 bi  = *(const float4*)&bias[c0];
    float4 as4 = *(const float4*)&aws[c0];
    float4 ad4 = *(const float4*)&awd[c0];
    float psr[4], pdr[4];
#pragma unroll
    for (int r = 0; r < 4; ++r) {
        float2 v0 = unpack2(acc[r][0]);
        float2 v1 = unpack2(acc[r][1]);
        float z0 = v0.x + bi.x, z1 = v0.y + bi.y;
        float z2 = v1.x + bi.z, z3 = v1.y + bi.w;
        int row = m0 + r0 + r;
        __half2 h0 = __floats2half2_rn(z0, z1);
        __half2 h1 = __floats2half2_rn(z2, z3);
        uint2 pk = make_uint2(*(unsigned*)&h0, *(unsigned*)&h1);
        *(uint2*)&g_z_h[row*32 + 2*tx] = pk;                 // STG.64
        psr[r] = fmaf(z3, as4.w, fmaf(z2, as4.z, fmaf(z1, as4.y, z0 * as4.x)));
        pdr[r] = fmaf(z3, ad4.w, fmaf(z2, ad4.z, fmaf(z1, ad4.y, z0 * ad4.x)));
    }
#pragma unroll
    for (int off = 1; off < 16; off <<= 1) {
#pragma unroll
        for (int r = 0; r < 4; ++r) {
            psr[r] += __shfl_xor_sync(FULLMASK, psr[r], off);
            pdr[r] += __shfl_xor_sync(FULLMASK, pdr[r], off);
        }
    }
    if (tx == 0) {
#pragma unroll
        for (int r = 0; r < 4; ++r) {
            g_zsrc[m0 + r0 + r] = psr[r];
            g_zdst[m0 + r0 + r] = pdr[r];
        }
    }
}

// ===========================================================================
// KCOS: cosine Gram + esrc/edst (R12 cos branch as own kernel). 64 CTAs.
// ===========================================================================
__global__ void __launch_bounds__(256)
kcos(const float* __restrict__ emb,
     const float* __restrict__ attn_w) {
    __shared__ float At[64*68];
    __shared__ float Bt[64*68];
    __shared__ float rni[64], rnj[64];
    int tid = threadIdx.x;
    int bb = blockIdx.x;
    int i0 = (bb >> 3) * 64, j0 = (bb & 7) * 64;
    for (int idx = tid; idx < 4096; idx += 256) {
        int r = idx >> 6, k = idx & 63;
        At[k*68 + r] = emb[(i0 + r)*64 + k];
        Bt[k*68 + r] = emb[(j0 + r)*64 + k];
    }
    __syncthreads();
    if (tid < 128) {
        int r = tid & 63;
        const float* T = (tid >= 64) ? Bt : At;
        float s = 0.f;
#pragma unroll
        for (int k = 0; k < 64; ++k) { float v = T[k*68 + r]; s = fmaf(v, v, s); }
        float inv = 1.0f / sqrtf(s);
        if (tid >= 64) rnj[r] = inv; else rni[r] = inv;
    } else if (bb < 8) {
        int r = tid & 63;
        int which = (tid >= 192);
        const float* awp = attn_w + (which ? 3*Dd : Dd);
        float acc = 0.f;
#pragma unroll
        for (int k = 0; k < 64; ++k)
            acc = fmaf(Bt[k*68 + r], awp[k], acc);
        if (which) g_edst[j0 + r] = acc;
        else       g_esrc[j0 + r] = acc;
    }
    __syncthreads();
    int tx = tid & 15, ty = tid >> 4;
    int r0 = ty * 4, c0 = tx * 4;
    float acc[4][4] = {};
#pragma unroll 8
    for (int k = 0; k < 64; ++k) {
        float4 a4 = *(const float4*)&At[k*68 + r0];
        float4 b4 = *(const float4*)&Bt[k*68 + c0];
        float av[4] = {a4.x, a4.y, a4.z, a4.w};
        float bv[4] = {b4.x, b4.y, b4.z, b4.w};
#pragma unroll
        for (int r = 0; r < 4; ++r)
#pragma unroll
            for (int c = 0; c < 4; ++c)
                acc[r][c] = fmaf(av[r], bv[c], acc[r][c]);
    }
    float rj[4];
#pragma unroll
    for (int c = 0; c < 4; ++c) rj[c] = rnj[c0 + c];
#pragma unroll
    for (int r = 0; r < 4; ++r) {
        float ri = rni[r0 + r];
        float4 o;
        o.x = acc[r][0] * ri * rj[0];
        o.y = acc[r][1] * ri * rj[1];
        o.z = acc[r][2] * ri * rj[2];
        o.w = acc[r][3] * ri * rj[3];
        *(float4*)&g_cos[(i0 + r0 + r)*Nn + j0 + c0] = o;
    }
}

// ===========================================================================
// K2: per-row top-20 (warp per row, 128 CTAs)
// ===========================================================================
__global__ void __launch_bounds__(128)
k2_topk() {
    int w    = blockIdx.x * 4 + (threadIdx.x >> 5);   // row 0..511
    int lane = threadIdx.x & 31;
    const float* row = g_cos + w * Nn;
    float v[16];
#pragma unroll
    for (int t = 0; t < 16; ++t) v[t] = row[t*32 + lane];
    float bv = v[0]; int bt = 0;
#pragma unroll
    for (int t = 1; t < 16; ++t) if (v[t] > bv) { bv = v[t]; bt = t; }
    for (int it = 0; it < KTOP; ++it) {
        float rv = bv; int ri = bt*32 + lane;
#pragma unroll
        for (int off = 16; off; off >>= 1) {
            float ov = __shfl_down_sync(FULLMASK, rv, off);
            int   oi = __shfl_down_sync(FULLMASK, ri, off);
            if (ov > rv || (ov == rv && oi < ri)) { rv = ov; ri = oi; }
        }
        ri = __shfl_sync(FULLMASK, ri, 0);
        if (lane == 0) {
            int F = w * KTOP + it;
            g_srcJ[(F >> 9) * Nn + (F & 511)] = ri;
        }
        if ((ri & 31) == lane) {
            int kt = ri >> 5;
#pragma unroll
            for (int t = 0; t < 16; ++t) if (t == kt) v[t] = -INFINITY;
            bv = v[0]; bt = 0;
#pragma unroll
            for (int t = 1; t < 16; ++t) if (v[t] > bv) { bv = v[t]; bt = t; }
        }
    }
}

// ===========================================================================
// KB: attention. 4 CTAs per batch (128 dst each), 512 threads, 2 CTAs/SM.
// z_h stride 36 half2 (144B rows, 16B-divisible -> STS.128 staging; gather
// banks (lane + 4s) mod 32 conflict-free).
// smem: als 20480 | z_h 512*36*4=73728 | ssrc 2048 | sdst 2048 = 98304 B
// ===========================================================================
__global__ void __launch_bounds__(512, 2)
kb_attn(const float* __restrict__ emb,
        const float* __restrict__ attn_b_p) {
    extern __shared__ char smc[];
    float2*  als  = (float2*)smc;                      // 128*20 (20,480B)
    __half2* z_h  = (__half2*)(smc + 20480);           // 512*36 (73,728B)
    float*   ssrc = (float*)(smc + 94208);             // 512
    float*   sdst = (float*)(smc + 96256);             // 512
    float*   wbufS = (float*)smc;                      // overlay on als
    float*   wbufQ = (float*)(smc + 4352);

    int b = blockIdx.x >> 2;
    int dbase = (blockIdx.x & 3) * 128;
    int tid = threadIdx.x;
    int w = tid >> 5, lane = tid & 31;

    {
        const uint4* zg = (const uint4*)(g_z_h + (size_t)b * Nn * 32);
        unsigned* zu = (unsigned*)z_h;
#pragma unroll
        for (int it = 0; it < 8; ++it) {
            int i = tid + it * 512;
            uint4 v = zg[i];
            int n = i >> 3, c0 = (i & 7) * 4;
            *(uint4*)(zu + n*36 + c0) = v;             // STS.128
        }
    }
    ssrc[tid] = g_zsrc[b*Nn + tid] + g_esrc[tid];
    sdst[tid] = g_zdst[b*Nn + tid] + g_edst[tid];
    __syncthreads();

    {
        const float ab = *attn_b_p;
        int dl = tid >> 2, q = tid & 3;
        int d = dbase + dl;
        float sd = sdst[d];
        float sc[5]; int si[5];
#pragma unroll
        for (int j5 = 0; j5 < 5; ++j5) {
            int j = q * 5 + j5;
            int s = g_srcJ[j * Nn + d];
            si[j5] = s;
            float x = ssrc[s] + sd + ab;
            sc[j5] = (x > 0.f) ? x : NEG_SLOPE * x;
        }
        float m = sc[0];
#pragma unroll
        for (int j5 = 1; j5 < 5; ++j5) m = fmaxf(m, sc[j5]);
        m = fmaxf(m, __shfl_xor_sync(FULLMASK, m, 1));
        m = fmaxf(m, __shfl_xor_sync(FULLMASK, m, 2));
        float p[5], ps = 0.f;
#pragma unroll
        for (int j5 = 0; j5 < 5; ++j5) { p[j5] = expf(sc[j5] - m); ps += p[j5]; }
        ps += __shfl_xor_sync(FULLMASK, ps, 1);
        ps += __shfl_xor_sync(FULLMASK, ps, 2);
        float inv = 1.0f / ps;
#pragma unroll
        for (int j5 = 0; j5 < 5; ++j5) {
            int j = q * 5 + j5;
            als[dl*KTOP + j] = make_float2(p[j5] * inv, __int_as_float(si[j5]));
        }
    }
    __syncthreads();

    float acc_s0 = 0.f, acc_q0 = 0.f, acc_s1 = 0.f, acc_q1 = 0.f;
    for (int r = 0; r < 8; r += 2) {
        int dlA = w * 8 + r, dlB = dlA + 1;
        float hA0 = 0.f, hA1 = 0.f, hB0 = 0.f, hB1 = 0.f;
#pragma unroll
        for (int jj = 0; jj < 10; ++jj) {
            float4 qA = *(const float4*)&als[dlA*KTOP + jj*2];
            float4 qB = *(const float4*)&als[dlB*KTOP + jj*2];
            int a0 = __float_as_int(qA.y), a1 = __float_as_int(qA.w);
            int b0 = __float_as_int(qB.y), b1 = __float_as_int(qB.w);
            float2 fa0 = __half22float2(z_h[a0*36 + lane]);
            float2 fa1 = __half22float2(z_h[a1*36 + lane]);
            float2 fb0 = __half22float2(z_h[b0*36 + lane]);
            float2 fb1 = __half22float2(z_h[b1*36 + lane]);
            hA0 = fmaf(qA.x, fa0.x, hA0); hA1 = fmaf(qA.x, fa0.y, hA1);
            hA0 = fmaf(qA.z, fa1.x, hA0); hA1 = fmaf(qA.z, fa1.y, hA1);
            hB0 = fmaf(qB.x, fb0.x, hB0); hB1 = fmaf(qB.x, fb0.y, hB1);
            hB0 = fmaf(qB.z, fb1.x, hB0); hB1 = fmaf(qB.z, fb1.y, hB1);
        }
        int dA = dbase + dlA, dB = dbase + dlB;
        float2 eA = *(const float2*)&emb[dA*64 + 2*lane];
        float2 eB = *(const float2*)&emb[dB*64 + 2*lane];
        float rA0 = hA0 * eA.x, rA1 = hA1 * eA.y;
        float rB0 = hB0 * eB.x, rB1 = hB1 * eB.y;
        g_rst_h[((size_t)b*Nn + dA)*32 + lane] = __floats2half2_rn(rA0, rA1);
        g_rst_h[((size_t)b*Nn + dB)*32 + lane] = __floats2half2_rn(rB0, rB1);
        acc_s0 += rA0 + rB0; acc_q0 = fmaf(rA0, rA0, fmaf(rB0, rB0, acc_q0));
        acc_s1 += rA1 + rB1; acc_q1 = fmaf(rA1, rA1, fmaf(rB1, rB1, acc_q1));
    }
    __syncthreads();
    wbufS[w*66 + 2*lane]     = acc_s0;
    wbufS[w*66 + 2*lane + 1] = acc_s1;
    wbufQ[w*66 + 2*lane]     = acc_q0;
    wbufQ[w*66 + 2*lane + 1] = acc_q1;
    __syncthreads();
    if (tid < 64) {
        float s = 0.f, q = 0.f;
#pragma unroll
        for (int ww = 0; ww < 16; ++ww) {
            s += wbufS[ww*66 + tid];
            q += wbufQ[ww*66 + tid];
        }
        atomicAdd(&g_sum[tid],   s);
        atomicAdd(&g_sumsq[tid], q);
    }
}

// ===========================================================================
// K6: BN finalize + BN + relu + output. 2 threads/row, 512 CTAs x 256 thr.
// ===========================================================================
__global__ void __launch_bounds__(256)
k6_out(const float* __restrict__ gamma,
       const float* __restrict__ beta,
       const float* __restrict__ out_w,
       const float* __restrict__ out_b_p,
       float* __restrict__ out) {
    __shared__ float sc_s[64], sh_s[64], wv[64];
    if (threadIdx.x < 64) {
        int t = threadIdx.x;
        const float inv_n = 1.0f / (float)(Bsz * Nn);
        float mu  = g_sum[t] * inv_n;
        float var = g_sumsq[t] * inv_n - mu * mu;
        float s   = gamma[t] / sqrtf(var + BN_EPS);
        sc_s[t] = s;
        sh_s[t] = beta[t] - mu * s;
        wv[t]   = out_w[t];
    }
    __syncthreads();
    int gt   = blockIdx.x * 256 + threadIdx.x;
    int row  = gt >> 1, half = gt & 1;             // 2 threads per row
    const uint4* rp = (const uint4*)(g_rst_h + (size_t)row * 32 + half * 16);
    uint4 u0 = rp[0], u1 = rp[1], u2 = rp[2], u3 = rp[3];   // MLP=4, 64B
    unsigned uu[16] = {u0.x,u0.y,u0.z,u0.w, u1.x,u1.y,u1.z,u1.w,
                       u2.x,u2.y,u2.z,u2.w, u3.x,u3.y,u3.z,u3.w};
    float s = 0.f;
    int cb = half * 32;
#pragma unroll
    for (int p = 0; p < 16; ++p) {
        float2 f0 = __half22float2(*(__half2*)&uu[p]);
        int ch = cb + 2*p;
        s += fmaxf(fmaf(f0.x, sc_s[ch],   sh_s[ch]),   0.f) * wv[ch];
        s += fmaxf(fmaf(f0.y, sc_s[ch+1], sh_s[ch+1]), 0.f) * wv[ch+1];
    }
    s += __shfl_xor_sync(FULLMASK, s, 1);
    if (half == 0) out[row] = s + *out_b_p;
}

// ---------------- launch ----------------------------------------------------
extern "C" void kernel_launch(void* const* d_in, const int* in_sizes, int n_in,
                              void* d_out, int out_size) {
    const float* data     = (const float*)d_in[0];
    const float* emb      = (const float*)d_in[1];
    const float* fc_w     = (const float*)d_in[2];
    const float* fc_b     = (const float*)d_in[3];
    const float* attn_w   = (const float*)d_in[4];
    const float* attn_b   = (const float*)d_in[5];
    const float* bn_gamma = (const float*)d_in[6];
    const float* bn_beta  = (const float*)d_in[7];
    const float* out_w    = (const float*)d_in[8];
    const float* out_b    = (const float*)d_in[9];
    float* out = (float*)d_out;

    const int KG_SMEM = 8896 * (int)sizeof(float);           // 35,584 B
    const int KB_SMEM = 98304;                                // bytes
    cudaFuncSetAttribute(kb_attn, cudaFuncAttributeMaxDynamicSharedMemorySize,
                         KB_SMEM);

    kgemm  <<<1024, 256, KG_SMEM>>>(data, fc_w, fc_b, attn_w);
    kcos   <<<64, 256>>>(emb, attn_w);
    k2_topk<<<128, 128>>>();
    kb_attn<<<Bsz * 4, 512, KB_SMEM>>>(emb, attn_b);
    k6_out <<<Bsz * Nn / 128, 256>>>(bn_gamma, bn_beta, out_w, out_b, out);
}

// round 14
// speedup vs baseline: 1.1738x; 1.1738x over previous
#include <cuda_runtime.h>
#include <cuda_fp16.h>
#include <math.h>

#define Bsz 128
#define Nn  512
#define Dd  64
#define KTOP 20
#define FULLMASK 0xFFFFFFFFu
#define NEG_SLOPE 0.2f
#define BN_EPS 1e-5f

typedef unsigned long long ull;

// ---------------- scratch (device globals; no allocations) ----------------
__device__ __align__(16) __half2 g_z_h[Bsz*Nn*32];    // z as half2 (8.4MB)
__device__ __align__(16) __half2 g_rst_h[Bsz*Nn*32];  // rst as half2 (8.4MB)
__device__ __align__(16) float g_cos[Nn*Nn];          // 1 MB
__device__ float g_zsrc[Bsz*Nn];
__device__ float g_zdst[Bsz*Nn];
__device__ int   g_srcJ[KTOP*Nn];                     // j-major: srcJ[j][d]
__device__ float g_esrc[Nn];
__device__ float g_edst[Nn];
__device__ __align__(16) float g_sum[Dd];
__device__ __align__(16) float g_sumsq[Dd];

// ---------------- f32x2 packed helpers -------------------------------------
__device__ __forceinline__ ull pack2(float x, float y) {
    ull r; asm("mov.b64 %0, {%1, %2};" : "=l"(r) : "f"(x), "f"(y)); return r;
}
__device__ __forceinline__ void fma2(ull& d, ull a, ull b) {
    asm("fma.rn.f32x2 %0, %1, %2, %0;" : "+l"(d) : "l"(a), "l"(b));
}
__device__ __forceinline__ float2 unpack2(ull v) {
    float2 r; asm("mov.b64 {%0, %1}, %2;" : "=f"(r.x), "=f"(r.y) : "l"(v)); return r;
}

// ===========================================================================
// K1A: blocks 0..63 -> cosine Gram (+ esrc/edst in blocks 0..7);
//      blocks 64..1087 -> z-GEMM (register epilogue). R12-identical.
// ===========================================================================
__global__ void __launch_bounds__(256)
k1a(const float* __restrict__ emb,
    const float* __restrict__ data,
    const float* __restrict__ fc_w,
    const float* __restrict__ fc_b,
    const float* __restrict__ attn_w) {
    extern __shared__ float sm[];
    int tid = threadIdx.x;

    if (blockIdx.x < 64) {
        float* At = sm;            // 64*68
        float* Bt = sm + 4352;     // 64*68
        float* rni = sm + 8704;    // 64
        float* rnj = rni + 64;     // 64
        int bb = blockIdx.x;
        int i0 = (bb >> 3) * 64, j0 = (bb & 7) * 64;
        for (int idx = tid; idx < 4096; idx += 256) {
            int r = idx >> 6, k = idx & 63;
            At[k*68 + r] = emb[(i0 + r)*64 + k];
            Bt[k*68 + r] = emb[(j0 + r)*64 + k];
        }
        __syncthreads();
        if (tid < 128) {
            int r = tid & 63;
            const float* T = (tid >= 64) ? Bt : At;
            float s = 0.f;
#pragma unroll
            for (int k = 0; k < 64; ++k) { float v = T[k*68 + r]; s = fmaf(v, v, s); }
            float inv = 1.0f / sqrtf(s);
            if (tid >= 64) rnj[r] = inv; else rni[r] = inv;
        } else if (bb < 8) {
            int r = tid & 63;
            int which = (tid >= 192);
            const float* awp = attn_w + (which ? 3*Dd : Dd);
            float acc = 0.f;
#pragma unroll
            for (int k = 0; k < 64; ++k)
                acc = fmaf(Bt[k*68 + r], awp[k], acc);
            if (which) g_edst[j0 + r] = acc;
            else       g_esrc[j0 + r] = acc;
        }
        __syncthreads();
        int tx = tid & 15, ty = tid >> 4;
        int r0 = ty * 4, c0 = tx * 4;
        float acc[4][4] = {};
#pragma unroll 8
        for (int k = 0; k < 64; ++k) {
            float4 a4 = *(const float4*)&At[k*68 + r0];
            float4 b4 = *(const float4*)&Bt[k*68 + c0];
            float av[4] = {a4.x, a4.y, a4.z, a4.w};
            float bv[4] = {b4.x, b4.y, b4.z, b4.w};
#pragma unroll
            for (int r = 0; r < 4; ++r)
#pragma unroll
                for (int c = 0; c < 4; ++c)
                    acc[r][c] = fmaf(av[r], bv[c], acc[r][c]);
        }
        float rj[4];
#pragma unroll
        for (int c = 0; c < 4; ++c) rj[c] = rnj[c0 + c];
#pragma unroll
        for (int r = 0; r < 4; ++r) {
            float ri = rni[r0 + r];
            float4 o;
            o.x = acc[r][0] * ri * rj[0];
            o.y = acc[r][1] * ri * rj[1];
            o.z = acc[r][2] * ri * rj[2];
            o.w = acc[r][3] * ri * rj[3];
            *(float4*)&g_cos[(i0 + r0 + r)*Nn + j0 + c0] = o;
        }
    } else {
        float* At  = sm;                      // 64*68 fp32
        ull*   wP  = (ull*)(sm + 4352);       // 64*34 packed w pairs
        float* aws = sm + 8704;               // 64
        float* awd = aws + 64;                // 64
        float* bias= awd + 64;                // 64  (ends at 8896)
        int zb = blockIdx.x - 64;             // 0..1023
        int m0 = zb * 64;

        if (zb == 0 && tid >= 128 && tid < 256) {
            int t = tid - 128;
            if (t < 64) g_sum[t] = 0.f; else g_sumsq[t - 64] = 0.f;
        }
        for (int idx = tid; idx < 1024; idx += 256) {
            int r = idx >> 4, kq = idx & 15;
            float4 v = *(const float4*)&data[(m0 + r)*64 + 4*kq];
            At[(4*kq+0)*68 + r] = v.x;
            At[(4*kq+1)*68 + r] = v.y;
            At[(4*kq+2)*68 + r] = v.z;
            At[(4*kq+3)*68 + r] = v.w;
        }
        for (int idx = tid; idx < 512; idx += 256) {
            int cp = idx >> 4, kq = idx & 15;
            float4 lo = *(const float4*)&fc_w[(2*cp)*64 + 4*kq];
            float4 hi = *(const float4*)&fc_w[(2*cp+1)*64 + 4*kq];
            wP[(4*kq+0)*34 + cp] = pack2(lo.x, hi.x);
            wP[(4*kq+1)*34 + cp] = pack2(lo.y, hi.y);
            wP[(4*kq+2)*34 + cp] = pack2(lo.z, hi.z);
            wP[(4*kq+3)*34 + cp] = pack2(lo.w, hi.w);
        }
        if (tid < 64) {
            bias[tid] = fc_b[tid];
            aws[tid]  = attn_w[tid];
            awd[tid]  = attn_w[128 + tid];
        }
        __syncthreads();

        int tx = tid & 15, ty = tid >> 4;
        int r0 = ty * 4;
        ull acc[4][2] = {};
#pragma unroll 8
        for (int k = 0; k < 64; ++k) {
            float4 a4 = *(const float4*)&At[k*68 + r0];
            ulonglong2 w2 = *(const ulonglong2*)&wP[k*34 + 2*tx];
            ull pa0 = pack2(a4.x, a4.x), pa1 = pack2(a4.y, a4.y);
            ull pa2 = pack2(a4.z, a4.z), pa3 = pack2(a4.w, a4.w);
            fma2(acc[0][0], pa0, w2.x); fma2(acc[0][1], pa0, w2.y);
            fma2(acc[1][0], pa1, w2.x); fma2(acc[1][1], pa1, w2.y);
            fma2(acc[2][0], pa2, w2.x); fma2(acc[2][1], pa2, w2.y);
            fma2(acc[3][0], pa3, w2.x); fma2(acc[3][1], pa3, w2.y);
        }
        int c0 = 4 * tx;
        float4 bi  = *(const float4*)&bias[c0];
        float4 as4 = *(const float4*)&aws[c0];
        float4 ad4 = *(const float4*)&awd[c0];
        float psr[4], pdr[4];
#pragma unroll
        for (int r = 0; r < 4; ++r) {
            float2 v0 = unpack2(acc[r][0]);
            float2 v1 = unpack2(acc[r][1]);
            float z0 = v0.x + bi.x, z1 = v0.y + bi.y;
            float z2 = v1.x + bi.z, z3 = v1.y + bi.w;
            int row = m0 + r0 + r;
            g_z_h[row*32 + 2*tx]     = __floats2half2_rn(z0, z1);
            g_z_h[row*32 + 2*tx + 1] = __floats2half2_rn(z2, z3);
            psr[r] = fmaf(z3, as4.w, fmaf(z2, as4.z, fmaf(z1, as4.y, z0 * as4.x)));
            pdr[r] = fmaf(z3, ad4.w, fmaf(z2, ad4.z, fmaf(z1, ad4.y, z0 * ad4.x)));
        }
#pragma unroll
        for (int off = 1; off < 16; off <<= 1) {
#pragma unroll
            for (int r = 0; r < 4; ++r) {
                psr[r] += __shfl_xor_sync(FULLMASK, psr[r], off);
                pdr[r] += __shfl_xor_sync(FULLMASK, pdr[r], off);
            }
        }
        if (tx == 0) {
#pragma unroll
            for (int r = 0; r < 4; ++r) {
                g_zsrc[m0 + r0 + r] = psr[r];
                g_zdst[m0 + r0 + r] = pdr[r];
            }
        }
    }
}

// ===========================================================================
// K2: per-row top-20 (warp per row, 128 CTAs)
// ===========================================================================
__global__ void __launch_bounds__(128)
k2_topk() {
    int w    = blockIdx.x * 4 + (threadIdx.x >> 5);   // row 0..511
    int lane = threadIdx.x & 31;
    const float* row = g_cos + w * Nn;
    float v[16];
#pragma unroll
    for (int t = 0; t < 16; ++t) v[t] = row[t*32 + lane];
    float bv = v[0]; int bt = 0;
#pragma unroll
    for (int t = 1; t < 16; ++t) if (v[t] > bv) { bv = v[t]; bt = t; }
    for (int it = 0; it < KTOP; ++it) {
        float rv = bv; int ri = bt*32 + lane;
#pragma unroll
        for (int off = 16; off; off >>= 1) {
            float ov = __shfl_down_sync(FULLMASK, rv, off);
            int   oi = __shfl_down_sync(FULLMASK, ri, off);
            if (ov > rv || (ov == rv && oi < ri)) { rv = ov; ri = oi; }
        }
        ri = __shfl_sync(FULLMASK, ri, 0);
        if (lane == 0) {
            int F = w * KTOP + it;
            g_srcJ[(F >> 9) * Nn + (F & 511)] = ri;
        }
        if ((ri & 31) == lane) {
            int kt = ri >> 5;
#pragma unroll
            for (int t = 0; t < 16; ++t) if (t == kt) v[t] = -INFINITY;
            bv = v[0]; bt = 0;
#pragma unroll
            for (int t = 1; t < 16; ++t) if (v[t] > bv) { bv = v[t]; bt = t; }
        }
    }
}

// ===========================================================================
// KB: attention. 4 CTAs per batch (128 dst each), 512 thr, 2 CTAs/SM.
// Gather: 4 channels/lane (LDS.64 z), dst split across half-warps.
// smem: als 20480 | z_h 512*34 half2 = 69632 | ssrc 2048 | sdst 2048 = 94208 B
// ===========================================================================
__global__ void __launch_bounds__(512, 2)
kb_attn(const float* __restrict__ emb,
        const float* __restrict__ attn_b_p) {
    extern __shared__ char smc[];
    float2*  als  = (float2*)smc;                      // 128*20 (20,480B)
    __half2* z_h  = (__half2*)(smc + 20480);           // 512*34 (69,632B)
    float*   ssrc = (float*)(smc + 90112);             // 512
    float*   sdst = (float*)(smc + 92160);             // 512
    float*   wbufS = (float*)smc;                      // overlay: 16*68 floats
    float*   wbufQ = (float*)(smc + 4352);             // overlay: 16*68 floats

    int b = blockIdx.x >> 2;
    int dbase = (blockIdx.x & 3) * 128;
    int tid = threadIdx.x;
    int w = tid >> 5, lane = tid & 31;

    {
        const uint4* zg = (const uint4*)(g_z_h + (size_t)b * Nn * 32);
        unsigned* zu = (unsigned*)z_h;
#pragma unroll
        for (int it = 0; it < 8; ++it) {
            int i = tid + it * 512;
            uint4 v = zg[i];
            int n = i >> 3, c0 = (i & 7) * 4;
            uint2* p = (uint2*)(zu + n*34 + c0);
            p[0] = make_uint2(v.x, v.y);
            p[1] = make_uint2(v.z, v.w);
        }
    }
    ssrc[tid] = g_zsrc[b*Nn + tid] + g_esrc[tid];
    sdst[tid] = g_zdst[b*Nn + tid] + g_edst[tid];
    __syncthreads();

    // ---- scores + softmax: 4 threads per dst, 5 edges each ----
    {
        const float ab = *attn_b_p;
        int dl = tid >> 2, q = tid & 3;
        int d = dbase + dl;
        float sd = sdst[d];
        float sc[5]; int si[5];
#pragma unroll
        for (int j5 = 0; j5 < 5; ++j5) {
            int j = q * 5 + j5;
            int s = g_srcJ[j * Nn + d];
            si[j5] = s;
            float x = ssrc[s] + sd + ab;
            sc[j5] = (x > 0.f) ? x : NEG_SLOPE * x;
        }
        float m = sc[0];
#pragma unroll
        for (int j5 = 1; j5 < 5; ++j5) m = fmaxf(m, sc[j5]);
        m = fmaxf(m, __shfl_xor_sync(FULLMASK, m, 1));
        m = fmaxf(m, __shfl_xor_sync(FULLMASK, m, 2));
        float p[5], ps = 0.f;
#pragma unroll
        for (int j5 = 0; j5 < 5; ++j5) { p[j5] = expf(sc[j5] - m); ps += p[j5]; }
        ps += __shfl_xor_sync(FULLMASK, ps, 1);
        ps += __shfl_xor_sync(FULLMASK, ps, 2);
        float inv = 1.0f / ps;
#pragma unroll
        for (int j5 = 0; j5 < 5; ++j5) {
            int j = q * 5 + j5;
            als[dl*KTOP + j] = make_float2(p[j5] * inv, __int_as_float(si[j5]));
        }
    }
    __syncthreads();

    // ---- gather: 2 dst per warp-pass via half-warp split; 4 ch per lane ----
    int hw = lane >> 4, l = lane & 15;
    float as0=0.f, as1=0.f, as2=0.f, as3=0.f;
    float aq0=0.f, aq1=0.f, aq2=0.f, aq3=0.f;
    for (int r = 0; r < 8; r += 2) {
        int dl = w * 8 + r + hw;
        float h0=0.f, h1=0.f, h2=0.f, h3=0.f;
#pragma unroll
        for (int jj = 0; jj < 10; ++jj) {
            float4 q = *(const float4*)&als[dl*KTOP + jj*2];
            int s0 = __float_as_int(q.y), s1 = __float_as_int(q.w);
            uint2 za = *(const uint2*)&z_h[s0*34 + 2*l];
            uint2 zb = *(const uint2*)&z_h[s1*34 + 2*l];
            float2 fa0 = __half22float2(*(__half2*)&za.x);
            float2 fa1 = __half22float2(*(__half2*)&za.y);
            float2 fb0 = __half22float2(*(__half2*)&zb.x);
            float2 fb1 = __half22float2(*(__half2*)&zb.y);
            h0 = fmaf(q.x, fa0.x, h0); h1 = fmaf(q.x, fa0.y, h1);
            h2 = fmaf(q.x, fa1.x, h2); h3 = fmaf(q.x, fa1.y, h3);
            h0 = fmaf(q.z, fb0.x, h0); h1 = fmaf(q.z, fb0.y, h1);
            h2 = fmaf(q.z, fb1.x, h2); h3 = fmaf(q.z, fb1.y, h3);
        }
        int d = dbase + dl;
        float4 e4 = *(const float4*)&emb[d*64 + 4*l];
        float r0v = h0 * e4.x, r1v = h1 * e4.y;
        float r2v = h2 * e4.z, r3v = h3 * e4.w;
        __half2 o0 = __floats2half2_rn(r0v, r1v);
        __half2 o1 = __floats2half2_rn(r2v, r3v);
        *(uint2*)&g_rst_h[((size_t)b*Nn + d)*32 + 2*l] =
            make_uint2(*(unsigned*)&o0, *(unsigned*)&o1);
        as0 += r0v; as1 += r1v; as2 += r2v; as3 += r3v;
        aq0 = fmaf(r0v, r0v, aq0); aq1 = fmaf(r1v, r1v, aq1);
        aq2 = fmaf(r2v, r2v, aq2); aq3 = fmaf(r3v, r3v, aq3);
    }
    // combine half-warps (same channel sets)
    as0 += __shfl_xor_sync(FULLMASK, as0, 16);
    as1 += __shfl_xor_sync(FULLMASK, as1, 16);
    as2 += __shfl_xor_sync(FULLMASK, as2, 16);
    as3 += __shfl_xor_sync(FULLMASK, as3, 16);
    aq0 += __shfl_xor_sync(FULLMASK, aq0, 16);
    aq1 += __shfl_xor_sync(FULLMASK, aq1, 16);
    aq2 += __shfl_xor_sync(FULLMASK, aq2, 16);
    aq3 += __shfl_xor_sync(FULLMASK, aq3, 16);
    __syncthreads();                      // als reads done; reuse region
    if (hw == 0) {
        *(float4*)&wbufS[w*68 + 4*l] = make_float4(as0, as1, as2, as3);
        *(float4*)&wbufQ[w*68 + 4*l] = make_float4(aq0, aq1, aq2, aq3);
    }
    __syncthreads();
    if (tid < 64) {
        float s = 0.f, q = 0.f;
#pragma unroll
        for (int ww = 0; ww < 16; ++ww) {
            s += wbufS[ww*68 + tid];
            q += wbufQ[ww*68 + tid];
        }
        atomicAdd(&g_sum[tid],   s);
        atomicAdd(&g_sumsq[tid], q);
    }
}

// ===========================================================================
// K6: BN finalize + BN + relu + output. 2 threads/row, 512 CTAs x 256 thr.
// ===========================================================================
__global__ void __launch_bounds__(256)
k6_out(const float* __restrict__ gamma,
       const float* __restrict__ beta,
       const float* __restrict__ out_w,
       const float* __restrict__ out_b_p,
       float* __restrict__ out) {
    __shared__ float sc_s[64], sh_s[64], wv[64];
    if (threadIdx.x < 64) {
        int t = threadIdx.x;
        const float inv_n = 1.0f / (float)(Bsz * Nn);
        float mu  = g_sum[t] * inv_n;
        float var = g_sumsq[t] * inv_n - mu * mu;
        float s   = gamma[t] / sqrtf(var + BN_EPS);
        sc_s[t] = s;
        sh_s[t] = beta[t] - mu * s;
        wv[t]   = out_w[t];
    }
    __syncthreads();
    int gt   = blockIdx.x * 256 + threadIdx.x;
    int row  = gt >> 1, half = gt & 1;
    const uint4* rp = (const uint4*)(g_rst_h + (size_t)row * 32 + half * 16);
    uint4 u0 = rp[0], u1 = rp[1], u2 = rp[2], u3 = rp[3];
    unsigned uu[16] = {u0.x,u0.y,u0.z,u0.w, u1.x,u1.y,u1.z,u1.w,
                       u2.x,u2.y,u2.z,u2.w, u3.x,u3.y,u3.z,u3.w};
    float s = 0.f;
    int cb = half * 32;
#pragma unroll
    for (int p = 0; p < 16; ++p) {
        float2 f0 = __half22float2(*(__half2*)&uu[p]);
        int ch = cb + 2*p;
        s += fmaxf(fmaf(f0.x, sc_s[ch],   sh_s[ch]),   0.f) * wv[ch];
        s += fmaxf(fmaf(f0.y, sc_s[ch+1], sh_s[ch+1]), 0.f) * wv[ch+1];
    }
    s += __shfl_xor_sync(FULLMASK, s, 1);
    if (half == 0) out[row] = s + *out_b_p;
}

// ---------------- launch ----------------------------------------------------
extern "C" void kernel_launch(void* const* d_in, const int* in_sizes, int n_in,
                              void* d_out, int out_size) {
    const float* data     = (const float*)d_in[0];
    const float* emb      = (const float*)d_in[1];
    const float* fc_w     = (const float*)d_in[2];
    const float* fc_b     = (const float*)d_in[3];
    const float* attn_w   = (const float*)d_in[4];
    const float* attn_b   = (const float*)d_in[5];
    const float* bn_gamma = (const float*)d_in[6];
    const float* bn_beta  = (const float*)d_in[7];
    const float* out_w    = (const float*)d_in[8];
    const float* out_b    = (const float*)d_in[9];
    float* out = (float*)d_out;

    const int K1A_SMEM = 8896 * (int)sizeof(float);          // 35,584 B
    const int KB_SMEM  = 94208;                               // bytes
    cudaFuncSetAttribute(k1a, cudaFuncAttributeMaxDynamicSharedMemorySize,
                         K1A_SMEM);
    cudaFuncSetAttribute(kb_attn, cudaFuncAttributeMaxDynamicSharedMemorySize,
                         KB_SMEM);

    k1a     <<<64 + 1024, 256, K1A_SMEM>>>(emb, data, fc_w, fc_b, attn_w);
    k2_topk <<<128, 128>>>();
    kb_attn <<<Bsz * 4, 512, KB_SMEM>>>(emb, attn_b);
    k6_out  <<<Bsz * Nn / 128, 256>>>(bn_gamma, bn_beta, out_w, out_b, out);
}

// round 15
// speedup vs baseline: 1.2081x; 1.0292x over previous
#include <cuda_runtime.h>
#include <cuda_fp16.h>
#include <math.h>

#define Bsz 128
#define Nn  512
#define Dd  64
#define KTOP 20
#define FULLMASK 0xFFFFFFFFu
#define NEG_SLOPE 0.2f
#define BN_EPS 1e-5f

typedef unsigned long long ull;

// ---------------- scratch (device globals; no allocations) ----------------
__device__ __align__(16) __half2 g_z_h[Bsz*Nn*32];    // z as half2 (8.4MB)
__device__ __align__(16) __half2 g_rst_h[Bsz*Nn*32];  // rst as half2 (8.4MB)
__device__ __align__(16) float g_cos[Nn*Nn];          // 1 MB
__device__ float g_zsrc[Bsz*Nn];
__device__ float g_zdst[Bsz*Nn];
__device__ int   g_srcJ[KTOP*Nn];                     // j-major: srcJ[j][d]
__device__ float g_esrc[Nn];
__device__ float g_edst[Nn];
__device__ __align__(16) float g_sum[Dd];
__device__ __align__(16) float g_sumsq[Dd];

// ---------------- f32x2 packed helpers -------------------------------------
__device__ __forceinline__ ull pack2(float x, float y) {
    ull r; asm("mov.b64 %0, {%1, %2};" : "=l"(r) : "f"(x), "f"(y)); return r;
}
__device__ __forceinline__ void fma2(ull& d, ull a, ull b) {
    asm("fma.rn.f32x2 %0, %1, %2, %0;" : "+l"(d) : "l"(a), "l"(b));
}
__device__ __forceinline__ float2 unpack2(ull v) {
    float2 r; asm("mov.b64 {%0, %1}, %2;" : "=f"(r.x), "=f"(r.y) : "l"(v)); return r;
}

// ===========================================================================
// K1A: blocks 0..63 -> cosine Gram (+ esrc/edst in blocks 0..7);
//      blocks 64..1087 -> z-GEMM (register epilogue). R14-identical.
// ===========================================================================
__global__ void __launch_bounds__(256)
k1a(const float* __restrict__ emb,
    const float* __restrict__ data,
    const float* __restrict__ fc_w,
    const float* __restrict__ fc_b,
    const float* __restrict__ attn_w) {
    extern __shared__ float sm[];
    int tid = threadIdx.x;

    if (blockIdx.x < 64) {
        float* At = sm;            // 64*68
        float* Bt = sm + 4352;     // 64*68
        float* rni = sm + 8704;    // 64
        float* rnj = rni + 64;     // 64
        int bb = blockIdx.x;
        int i0 = (bb >> 3) * 64, j0 = (bb & 7) * 64;
        for (int idx = tid; idx < 4096; idx += 256) {
            int r = idx >> 6, k = idx & 63;
            At[k*68 + r] = emb[(i0 + r)*64 + k];
            Bt[k*68 + r] = emb[(j0 + r)*64 + k];
        }
        __syncthreads();
        if (tid < 128) {
            int r = tid & 63;
            const float* T = (tid >= 64) ? Bt : At;
            float s = 0.f;
#pragma unroll
            for (int k = 0; k < 64; ++k) { float v = T[k*68 + r]; s = fmaf(v, v, s); }
            float inv = 1.0f / sqrtf(s);
            if (tid >= 64) rnj[r] = inv; else rni[r] = inv;
        } else if (bb < 8) {
            int r = tid & 63;
            int which = (tid >= 192);
            const float* awp = attn_w + (which ? 3*Dd : Dd);
            float acc = 0.f;
#pragma unroll
            for (int k = 0; k < 64; ++k)
                acc = fmaf(Bt[k*68 + r], awp[k], acc);
            if (which) g_edst[j0 + r] = acc;
            else       g_esrc[j0 + r] = acc;
        }
        __syncthreads();
        int tx = tid & 15, ty = tid >> 4;
        int r0 = ty * 4, c0 = tx * 4;
        float acc[4][4] = {};
#pragma unroll 8
        for (int k = 0; k < 64; ++k) {
            float4 a4 = *(const float4*)&At[k*68 + r0];
            float4 b4 = *(const float4*)&Bt[k*68 + c0];
            float av[4] = {a4.x, a4.y, a4.z, a4.w};
            float bv[4] = {b4.x, b4.y, b4.z, b4.w};
#pragma unroll
            for (int r = 0; r < 4; ++r)
#pragma unroll
                for (int c = 0; c < 4; ++c)
                    acc[r][c] = fmaf(av[r], bv[c], acc[r][c]);
        }
        float rj[4];
#pragma unroll
        for (int c = 0; c < 4; ++c) rj[c] = rnj[c0 + c];
#pragma unroll
        for (int r = 0; r < 4; ++r) {
            float ri = rni[r0 + r];
            float4 o;
            o.x = acc[r][0] * ri * rj[0];
            o.y = acc[r][1] * ri * rj[1];
            o.z = acc[r][2] * ri * rj[2];
            o.w = acc[r][3] * ri * rj[3];
            *(float4*)&g_cos[(i0 + r0 + r)*Nn + j0 + c0] = o;
        }
    } else {
        float* At  = sm;                      // 64*68 fp32
        ull*   wP  = (ull*)(sm + 4352);       // 64*34 packed w pairs
        float* aws = sm + 8704;               // 64
        float* awd = aws + 64;                // 64
        float* bias= awd + 64;                // 64  (ends at 8896)
        int zb = blockIdx.x - 64;             // 0..1023
        int m0 = zb * 64;

        if (zb == 0 && tid >= 128 && tid < 256) {
            int t = tid - 128;
            if (t < 64) g_sum[t] = 0.f; else g_sumsq[t - 64] = 0.f;
        }
        for (int idx = tid; idx < 1024; idx += 256) {
            int r = idx >> 4, kq = idx & 15;
            float4 v = *(const float4*)&data[(m0 + r)*64 + 4*kq];
            At[(4*kq+0)*68 + r] = v.x;
            At[(4*kq+1)*68 + r] = v.y;
            At[(4*kq+2)*68 + r] = v.z;
            At[(4*kq+3)*68 + r] = v.w;
        }
        for (int idx = tid; idx < 512; idx += 256) {
            int cp = idx >> 4, kq = idx & 15;
            float4 lo = *(const float4*)&fc_w[(2*cp)*64 + 4*kq];
            float4 hi = *(const float4*)&fc_w[(2*cp+1)*64 + 4*kq];
            wP[(4*kq+0)*34 + cp] = pack2(lo.x, hi.x);
            wP[(4*kq+1)*34 + cp] = pack2(lo.y, hi.y);
            wP[(4*kq+2)*34 + cp] = pack2(lo.z, hi.z);
            wP[(4*kq+3)*34 + cp] = pack2(lo.w, hi.w);
        }
        if (tid < 64) {
            bias[tid] = fc_b[tid];
            aws[tid]  = attn_w[tid];
            awd[tid]  = attn_w[128 + tid];
        }
        __syncthreads();

        int tx = tid & 15, ty = tid >> 4;
        int r0 = ty * 4;
        ull acc[4][2] = {};
#pragma unroll 8
        for (int k = 0; k < 64; ++k) {
            float4 a4 = *(const float4*)&At[k*68 + r0];
            ulonglong2 w2 = *(const ulonglong2*)&wP[k*34 + 2*tx];
            ull pa0 = pack2(a4.x, a4.x), pa1 = pack2(a4.y, a4.y);
            ull pa2 = pack2(a4.z, a4.z), pa3 = pack2(a4.w, a4.w);
            fma2(acc[0][0], pa0, w2.x); fma2(acc[0][1], pa0, w2.y);
            fma2(acc[1][0], pa1, w2.x); fma2(acc[1][1], pa1, w2.y);
            fma2(acc[2][0], pa2, w2.x); fma2(acc[2][1], pa2, w2.y);
            fma2(acc[3][0], pa3, w2.x); fma2(acc[3][1], pa3, w2.y);
        }
        int c0 = 4 * tx;
        float4 bi  = *(const float4*)&bias[c0];
        float4 as4 = *(const float4*)&aws[c0];
        float4 ad4 = *(const float4*)&awd[c0];
        float psr[4], pdr[4];
#pragma unroll
        for (int r = 0; r < 4; ++r) {
            float2 v0 = unpack2(acc[r][0]);
            float2 v1 = unpack2(acc[r][1]);
            float z0 = v0.x + bi.x, z1 = v0.y + bi.y;
            float z2 = v1.x + bi.z, z3 = v1.y + bi.w;
            int row = m0 + r0 + r;
            g_z_h[row*32 + 2*tx]     = __floats2half2_rn(z0, z1);
            g_z_h[row*32 + 2*tx + 1] = __floats2half2_rn(z2, z3);
            psr[r] = fmaf(z3, as4.w, fmaf(z2, as4.z, fmaf(z1, as4.y, z0 * as4.x)));
            pdr[r] = fmaf(z3, ad4.w, fmaf(z2, ad4.z, fmaf(z1, ad4.y, z0 * ad4.x)));
        }
#pragma unroll
        for (int off = 1; off < 16; off <<= 1) {
#pragma unroll
            for (int r = 0; r < 4; ++r) {
                psr[r] += __shfl_xor_sync(FULLMASK, psr[r], off);
                pdr[r] += __shfl_xor_sync(FULLMASK, pdr[r], off);
            }
        }
        if (tx == 0) {
#pragma unroll
            for (int r = 0; r < 4; ++r) {
                g_zsrc[m0 + r0 + r] = psr[r];
                g_zdst[m0 + r0 + r] = pdr[r];
            }
        }
    }
}

// ===========================================================================
// K2: per-row top-20 (warp per row, 128 CTAs)
// ===========================================================================
__global__ void __launch_bounds__(128)
k2_topk() {
    int w    = blockIdx.x * 4 + (threadIdx.x >> 5);   // row 0..511
    int lane = threadIdx.x & 31;
    const float* row = g_cos + w * Nn;
    float v[16];
#pragma unroll
    for (int t = 0; t < 16; ++t) v[t] = row[t*32 + lane];
    float bv = v[0]; int bt = 0;
#pragma unroll
    for (int t = 1; t < 16; ++t) if (v[t] > bv) { bv = v[t]; bt = t; }
    for (int it = 0; it < KTOP; ++it) {
        float rv = bv; int ri = bt*32 + lane;
#pragma unroll
        for (int off = 16; off; off >>= 1) {
            float ov = __shfl_down_sync(FULLMASK, rv, off);
            int   oi = __shfl_down_sync(FULLMASK, ri, off);
            if (ov > rv || (ov == rv && oi < ri)) { rv = ov; ri = oi; }
        }
        ri = __shfl_sync(FULLMASK, ri, 0);
        if (lane == 0) {
            int F = w * KTOP + it;
            g_srcJ[(F >> 9) * Nn + (F & 511)] = ri;
        }
        if ((ri & 31) == lane) {
            int kt = ri >> 5;
#pragma unroll
            for (int t = 0; t < 16; ++t) if (t == kt) v[t] = -INFINITY;
            bv = v[0]; bt = 0;
#pragma unroll
            for (int t = 1; t < 16; ++t) if (v[t] > bv) { bv = v[t]; bt = t; }
        }
    }
}

// ===========================================================================
// KB: attention. 4 CTAs per batch (128 dst each), 512 thr, 2 CTAs/SM.
// Gather: HFMA2 accumulation (alpha pre-packed as dup half2 in als entry),
// two 10-edge fp16 segments promoted to fp32. 4 channels/lane, half-warp dst.
// smem: als2 20480 | z_h 512*34 half2 = 69632 | ssrc 2048 | sdst 2048 = 94208 B
// ===========================================================================
__global__ void __launch_bounds__(512, 2)
kb_attn(const float* __restrict__ emb,
        const float* __restrict__ attn_b_p) {
    extern __shared__ char smc[];
    uint2*   als2 = (uint2*)smc;                       // 128*20*8B (20,480B)
    __half2* z_h  = (__half2*)(smc + 20480);           // 512*34 (69,632B)
    float*   ssrc = (float*)(smc + 90112);             // 512
    float*   sdst = (float*)(smc + 92160);             // 512
    float*   wbufS = (float*)smc;                      // overlay: 16*68 floats
    float*   wbufQ = (float*)(smc + 4352);             // overlay: 16*68 floats

    int b = blockIdx.x >> 2;
    int dbase = (blockIdx.x & 3) * 128;
    int tid = threadIdx.x;
    int w = tid >> 5, lane = tid & 31;

    {
        const uint4* zg = (const uint4*)(g_z_h + (size_t)b * Nn * 32);
        unsigned* zu = (unsigned*)z_h;
#pragma unroll
        for (int it = 0; it < 8; ++it) {
            int i = tid + it * 512;
            uint4 v = zg[i];
            int n = i >> 3, c0 = (i & 7) * 4;
            uint2* p = (uint2*)(zu + n*34 + c0);
            p[0] = make_uint2(v.x, v.y);
            p[1] = make_uint2(v.z, v.w);
        }
    }
    ssrc[tid] = g_zsrc[b*Nn + tid] + g_esrc[tid];
    sdst[tid] = g_zdst[b*Nn + tid] + g_edst[tid];
    __syncthreads();

    // ---- scores + softmax: 4 threads per dst, 5 edges each ----
    {
        const float ab = *attn_b_p;
        int dl = tid >> 2, q = tid & 3;
        int d = dbase + dl;
        float sd = sdst[d];
        float sc[5]; int si[5];
#pragma unroll
        for (int j5 = 0; j5 < 5; ++j5) {
            int j = q * 5 + j5;
            int s = g_srcJ[j * Nn + d];
            si[j5] = s;
            float x = ssrc[s] + sd + ab;
            sc[j5] = (x > 0.f) ? x : NEG_SLOPE * x;
        }
        float m = sc[0];
#pragma unroll
        for (int j5 = 1; j5 < 5; ++j5) m = fmaxf(m, sc[j5]);
        m = fmaxf(m, __shfl_xor_sync(FULLMASK, m, 1));
        m = fmaxf(m, __shfl_xor_sync(FULLMASK, m, 2));
        float p[5], ps = 0.f;
#pragma unroll
        for (int j5 = 0; j5 < 5; ++j5) { p[j5] = expf(sc[j5] - m); ps += p[j5]; }
        ps += __shfl_xor_sync(FULLMASK, ps, 1);
        ps += __shfl_xor_sync(FULLMASK, ps, 2);
        float inv = 1.0f / ps;
#pragma unroll
        for (int j5 = 0; j5 < 5; ++j5) {
            int j = q * 5 + j5;
            __half2 ah2 = __float2half2_rn(p[j5] * inv);
            als2[dl*KTOP + j] = make_uint2(*(unsigned*)&ah2, (unsigned)si[j5]);
        }
    }
    __syncthreads();

    // ---- gather: HFMA2, 2 dst per warp-pass (half-warp split), 4 ch/lane ---
    int hw = lane >> 4, l = lane & 15;
    float as0=0.f, as1=0.f, as2=0.f, as3=0.f;
    float aq0=0.f, aq1=0.f, aq2=0.f, aq3=0.f;
    const __half2 hz = __float2half2_rn(0.f);
    for (int r = 0; r < 8; r += 2) {
        int dl = w * 8 + r + hw;
        float h0=0.f, h1=0.f, h2=0.f, h3=0.f;
#pragma unroll
        for (int seg = 0; seg < 2; ++seg) {
            __half2 g0 = hz, g1 = hz;
#pragma unroll
            for (int jj = 0; jj < 5; ++jj) {
                uint4 q = *(const uint4*)&als2[dl*KTOP + seg*10 + jj*2];
                uint2 za = *(const uint2*)&z_h[(int)q.y*34 + 2*l];
                uint2 zb = *(const uint2*)&z_h[(int)q.w*34 + 2*l];
                __half2 a0 = *(__half2*)&q.x;
                __half2 a1 = *(__half2*)&q.z;
                g0 = __hfma2(a0, *(__half2*)&za.x, g0);
                g1 = __hfma2(a0, *(__half2*)&za.y, g1);
                g0 = __hfma2(a1, *(__half2*)&zb.x, g0);
                g1 = __hfma2(a1, *(__half2*)&zb.y, g1);
            }
            float2 f0 = __half22float2(g0);
            float2 f1 = __half22float2(g1);
            h0 += f0.x; h1 += f0.y; h2 += f1.x; h3 += f1.y;
        }
        int d = dbase + dl;
        float4 e4 = *(const float4*)&emb[d*64 + 4*l];
        float r0v = h0 * e4.x, r1v = h1 * e4.y;
        float r2v = h2 * e4.z, r3v = h3 * e4.w;
        __half2 o0 = __floats2half2_rn(r0v, r1v);
        __half2 o1 = __floats2half2_rn(r2v, r3v);
        *(uint2*)&g_rst_h[((size_t)b*Nn + d)*32 + 2*l] =
            make_uint2(*(unsigned*)&o0, *(unsigned*)&o1);
        as0 += r0v; as1 += r1v; as2 += r2v; as3 += r3v;
        aq0 = fmaf(r0v, r0v, aq0); aq1 = fmaf(r1v, r1v, aq1);
        aq2 = fmaf(r2v, r2v, aq2); aq3 = fmaf(r3v, r3v, aq3);
    }
    as0 += __shfl_xor_sync(FULLMASK, as0, 16);
    as1 += __shfl_xor_sync(FULLMASK, as1, 16);
    as2 += __shfl_xor_sync(FULLMASK, as2, 16);
    as3 += __shfl_xor_sync(FULLMASK, as3, 16);
    aq0 += __shfl_xor_sync(FULLMASK, aq0, 16);
    aq1 += __shfl_xor_sync(FULLMASK, aq1, 16);
    aq2 += __shfl_xor_sync(FULLMASK, aq2, 16);
    aq3 += __shfl_xor_sync(FULLMASK, aq3, 16);
    __syncthreads();                      // als2 reads done; reuse region
    if (hw == 0) {
        *(float4*)&wbufS[w*68 + 4*l] = make_float4(as0, as1, as2, as3);
        *(float4*)&wbufQ[w*68 + 4*l] = make_float4(aq0, aq1, aq2, aq3);
    }
    __syncthreads();
    if (tid < 64) {
        float s = 0.f, q = 0.f;
#pragma unroll
        for (int ww = 0; ww < 16; ++ww) {
            s += wbufS[ww*68 + tid];
            q += wbufQ[ww*68 + tid];
        }
        atomicAdd(&g_sum[tid],   s);
        atomicAdd(&g_sumsq[tid], q);
    }
}

// ===========================================================================
// K6: BN finalize + BN + relu + output. 2 threads/row, 512 CTAs x 256 thr.
// ===========================================================================
__global__ void __launch_bounds__(256)
k6_out(const float* __restrict__ gamma,
       const float* __restrict__ beta,
       const float* __restrict__ out_w,
       const float* __restrict__ out_b_p,
       float* __restrict__ out) {
    __shared__ float sc_s[64], sh_s[64], wv[64];
    if (threadIdx.x < 64) {
        int t = threadIdx.x;
        const float inv_n = 1.0f / (float)(Bsz * Nn);
        float mu  = g_sum[t] * inv_n;
        float var = g_sumsq[t] * inv_n - mu * mu;
        float s   = gamma[t] / sqrtf(var + BN_EPS);
        sc_s[t] = s;
        sh_s[t] = beta[t] - mu * s;
        wv[t]   = out_w[t];
    }
    __syncthreads();
    int gt   = blockIdx.x * 256 + threadIdx.x;
    int row  = gt >> 1, half = gt & 1;
    const uint4* rp = (const uint4*)(g_rst_h + (size_t)row * 32 + half * 16);
    uint4 u0 = rp[0], u1 = rp[1], u2 = rp[2], u3 = rp[3];
    unsigned uu[16] = {u0.x,u0.y,u0.z,u0.w, u1.x,u1.y,u1.z,u1.w,
                       u2.x,u2.y,u2.z,u2.w, u3.x,u3.y,u3.z,u3.w};
    float s = 0.f;
    int cb = half * 32;
#pragma unroll
    for (int p = 0; p < 16; ++p) {
        float2 f0 = __half22float2(*(__half2*)&uu[p]);
        int ch = cb + 2*p;
        s += fmaxf(fmaf(f0.x, sc_s[ch],   sh_s[ch]),   0.f) * wv[ch];
        s += fmaxf(fmaf(f0.y, sc_s[ch+1], sh_s[ch+1]), 0.f) * wv[ch+1];
    }
    s += __shfl_xor_sync(FULLMASK, s, 1);
    if (half == 0) out[row] = s + *out_b_p;
}

// ---------------- launch ----------------------------------------------------
extern "C" void kernel_launch(void* const* d_in, const int* in_sizes, int n_in,
                              void* d_out, int out_size) {
    const float* data     = (const float*)d_in[0];
    const float* emb      = (const float*)d_in[1];
    const float* fc_w     = (const float*)d_in[2];
    const float* fc_b     = (const float*)d_in[3];
    const float* attn_w   = (const float*)d_in[4];
    const float* attn_b   = (const float*)d_in[5];
    const float* bn_gamma = (const float*)d_in[6];
    const float* bn_beta  = (const float*)d_in[7];
    const float* out_w    = (const float*)d_in[8];
    const float* out_b    = (const float*)d_in[9];
    float* out = (float*)d_out;

    const int K1A_SMEM = 8896 * (int)sizeof(float);          // 35,584 B
    const int KB_SMEM  = 94208;                               // bytes
    cudaFuncSetAttribute(k1a, cudaFuncAttributeMaxDynamicSharedMemorySize,
                         K1A_SMEM);
    cudaFuncSetAttribute(kb_attn, cudaFuncAttributeMaxDynamicSharedMemorySize,
                         KB_SMEM);

    k1a     <<<64 + 1024, 256, K1A_SMEM>>>(emb, data, fc_w, fc_b, attn_w);
    k2_topk <<<128, 128>>>();
    kb_attn <<<Bsz * 4, 512, KB_SMEM>>>(emb, attn_b);
    k6_out  <<<Bsz * Nn / 128, 256>>>(bn_gamma, bn_beta, out_w, out_b, out);
}